// round 1
// baseline (speedup 1.0000x reference)
#include <cuda_runtime.h>

// Problem constants (fixed by the reference)
constexpr int N  = 100000;
constexpr int E  = 1600000;
constexpr int IN = 32;
constexpr int H  = 64;
constexpr int L  = 16;
constexpr int G  = 64;

#define CDIV(a, b) (((a) + (b) - 1) / (b))

// ---------------- device scratch (no allocations allowed) ----------------
__device__ float g_buf0[N * H];   // xw / aggregation input
__device__ float g_buf1[N * H];   // layer activations
__device__ float g_buf2[N * H];   // aggregation output
__device__ float g_dinv[N];       // deg -> rsqrt(deg)
__device__ float g_coef[E];       // dinv[src]*dinv[dst], reused by all 5 convs
__device__ float g_pool[G * H];
__device__ float g_cnt[G];
__device__ float g_z[G * L];

// ---------------- degree / coefficients ----------------
__global__ void k_deg_init() {
    int i = blockIdx.x * blockDim.x + threadIdx.x;
    if (i < N) g_dinv[i] = 1.0f;  // self-loop
}

__global__ void k_deg_acc(const int* __restrict__ dst) {
    int e = blockIdx.x * blockDim.x + threadIdx.x;
    if (e < E) atomicAdd(&g_dinv[dst[e]], 1.0f);
}

__global__ void k_dinv() {
    int i = blockIdx.x * blockDim.x + threadIdx.x;
    if (i < N) g_dinv[i] = rsqrtf(g_dinv[i]);
}

__global__ void k_coef(const int* __restrict__ src, const int* __restrict__ dst) {
    int e = blockIdx.x * blockDim.x + threadIdx.x;
    if (e < E) g_coef[e] = g_dinv[src[e]] * g_dinv[dst[e]];
}

// ---------------- self-loop init:  Y = X * dinv^2 ----------------
template <int C>
__global__ void k_selfinit(const float* __restrict__ X, float* __restrict__ Y) {
    constexpr int Q = C / 4;
    int idx = blockIdx.x * blockDim.x + threadIdx.x;
    if (idx >= N * Q) return;
    int i = idx / Q, q = idx % Q;
    float d = g_dinv[i];
    float s = d * d;
    float4 v = *reinterpret_cast<const float4*>(X + i * C + q * 4);
    float4 o;
    o.x = v.x * s; o.y = v.y * s; o.z = v.z * s; o.w = v.w * s;
    *reinterpret_cast<float4*>(Y + i * C + q * 4) = o;
}

// ---------------- edge scatter:  Y[dst] += coef * X[src] ----------------
template <int C>
__global__ void k_scatter(const int* __restrict__ src, const int* __restrict__ dst,
                          const float* __restrict__ X, float* __restrict__ Y) {
    constexpr int Q = C / 4;
    int idx = blockIdx.x * blockDim.x + threadIdx.x;
    int e = idx / Q, q = idx % Q;
    if (e >= E) return;
    float cf = g_coef[e];
    int s = src[e], d = dst[e];
    float4 v = *reinterpret_cast<const float4*>(X + s * C + q * 4);
    float* o = Y + d * C + q * 4;
    atomicAdd(o + 0, v.x * cf);
    atomicAdd(o + 1, v.y * cf);
    atomicAdd(o + 2, v.z * cf);
    atomicAdd(o + 3, v.w * cf);
}

// ---------------- dense per-node matmul (W in smem) ----------------
template <int CIN, int COUT, bool BIAS, bool RELU>
__global__ void k_matmul(const float* __restrict__ X, const float* __restrict__ W,
                         const float* __restrict__ b, float* __restrict__ Y) {
    constexpr int ROWS = 256 / COUT;
    __shared__ float sW[CIN * COUT];
    __shared__ float sX[ROWS * CIN];
    int t = threadIdx.x;
    for (int i = t; i < CIN * COUT; i += 256) sW[i] = W[i];
    int row0 = blockIdx.x * ROWS;
    for (int i = t; i < ROWS * CIN; i += 256) {
        int r = row0 + i / CIN;
        sX[i] = (r < N) ? X[r * CIN + (i % CIN)] : 0.0f;
    }
    __syncthreads();
    int r = t / COUT, c = t % COUT;
    int row = row0 + r;
    if (row >= N) return;
    float acc = BIAS ? b[c] : 0.0f;
#pragma unroll
    for (int k = 0; k < CIN; k++) acc = fmaf(sX[r * CIN + k], sW[k * COUT + c], acc);
    Y[row * COUT + c] = RELU ? fmaxf(acc, 0.0f) : acc;
}

// ---------------- bias (+relu) elementwise ----------------
template <int C, bool RELU>
__global__ void k_bias(const float* __restrict__ X, const float* __restrict__ b,
                       float* __restrict__ Y) {
    int idx = blockIdx.x * blockDim.x + threadIdx.x;
    if (idx >= N * C) return;
    float v = X[idx] + b[idx % C];
    Y[idx] = RELU ? fmaxf(v, 0.0f) : v;
}

// ---------------- global mean pool ----------------
__global__ void k_pool_init() {
    int idx = blockIdx.x * blockDim.x + threadIdx.x;
    if (idx < G * H) g_pool[idx] = 0.0f;
    if (idx < G) g_cnt[idx] = 0.0f;
}

__global__ void k_pool_acc(const int* __restrict__ batch, const float* __restrict__ Hf) {
    int idx = blockIdx.x * blockDim.x + threadIdx.x;
    if (idx >= N * H) return;
    int i = idx / H, c = idx % H;
    atomicAdd(&g_pool[batch[i] * H + c], Hf[idx]);
}

__global__ void k_pool_cnt(const int* __restrict__ batch) {
    int i = blockIdx.x * blockDim.x + threadIdx.x;
    if (i < N) atomicAdd(&g_cnt[batch[i]], 1.0f);
}

// ---------------- latent projection: z = mean @ W_proj + b ----------------
__global__ void k_z(const float* __restrict__ Wp, const float* __restrict__ bp,
                    float* __restrict__ out_z) {
    int t = threadIdx.x;  // 1024 threads = G*L
    int g = t / L, l = t % L;
    float inv = 1.0f / fmaxf(g_cnt[g], 1.0f);
    float acc = bp[l];
#pragma unroll
    for (int c = 0; c < H; c++) acc = fmaf(g_pool[g * H + c] * inv, Wp[c * L + l], acc);
    g_z[t] = acc;
    out_z[t] = acc;
}

// ---------------- decoder broadcast: d = relu(z[batch] @ W_dec_proj + b) ----------------
__global__ void k_dec_bcast(const int* __restrict__ batch, const float* __restrict__ W,
                            const float* __restrict__ b, float* __restrict__ Y) {
    int idx = blockIdx.x * blockDim.x + threadIdx.x;
    if (idx >= N * H) return;
    int i = idx / H, c = idx % H;
    int gid = batch[i];
    float acc = b[c];
#pragma unroll
    for (int l = 0; l < L; l++) acc = fmaf(g_z[gid * L + l], W[l * H + c], acc);
    Y[idx] = fmaxf(acc, 0.0f);
}

// ---------------- launcher ----------------
extern "C" void kernel_launch(void* const* d_in, const int* in_sizes, int n_in,
                              void* d_out, int out_size) {
    const float* x       = (const float*)d_in[0];
    const int*   ei      = (const int*)d_in[1];
    const int*   src     = ei;
    const int*   dst     = ei + E;
    const int*   batch   = (const int*)d_in[2];
    const float* W_enc0  = (const float*)d_in[3];
    const float* b_enc0  = (const float*)d_in[4];
    const float* W_enc1  = (const float*)d_in[5];
    const float* b_enc1  = (const float*)d_in[6];
    const float* W_enc2  = (const float*)d_in[7];
    const float* b_enc2  = (const float*)d_in[8];
    const float* W_proj  = (const float*)d_in[9];
    const float* b_proj  = (const float*)d_in[10];
    const float* W_dproj = (const float*)d_in[11];
    const float* b_dproj = (const float*)d_in[12];
    const float* W_dec0  = (const float*)d_in[13];
    const float* b_dec0  = (const float*)d_in[14];
    const float* W_dec1  = (const float*)d_in[15];
    const float* b_dec1  = (const float*)d_in[16];

    float* out_recon = (float*)d_out;             // [N, IN]
    float* out_z     = (float*)d_out + N * IN;    // [G, L]

    float* buf0; cudaGetSymbolAddress((void**)&buf0, g_buf0);
    float* buf1; cudaGetSymbolAddress((void**)&buf1, g_buf1);
    float* buf2; cudaGetSymbolAddress((void**)&buf2, g_buf2);

    const int T = 256;

    // degrees + edge coefficients (reused by all 5 convs)
    k_deg_init<<<CDIV(N, T), T>>>();
    k_deg_acc<<<CDIV(E, T), T>>>(dst);
    k_dinv<<<CDIV(N, T), T>>>();
    k_coef<<<CDIV(E, T), T>>>(src, dst);

    // ---- enc0: aggregate x (C=32) first, then matmul 32->64 + bias + relu
    k_selfinit<IN><<<CDIV(N * IN / 4, T), T>>>(x, buf0);
    k_scatter<IN><<<CDIV(E * (IN / 4), T), T>>>(src, dst, x, buf0);
    k_matmul<IN, H, true, true><<<CDIV(N, 256 / H), 256>>>(buf0, W_enc0, b_enc0, buf1);

    // ---- enc1: matmul 64->64, aggregate, bias+relu
    k_matmul<H, H, false, false><<<CDIV(N, 256 / H), 256>>>(buf1, W_enc1, nullptr, buf0);
    k_selfinit<H><<<CDIV(N * H / 4, T), T>>>(buf0, buf2);
    k_scatter<H><<<CDIV(E * (H / 4), T), T>>>(src, dst, buf0, buf2);
    k_bias<H, true><<<CDIV(N * H, T), T>>>(buf2, b_enc1, buf1);

    // ---- enc2
    k_matmul<H, H, false, false><<<CDIV(N, 256 / H), 256>>>(buf1, W_enc2, nullptr, buf0);
    k_selfinit<H><<<CDIV(N * H / 4, T), T>>>(buf0, buf2);
    k_scatter<H><<<CDIV(E * (H / 4), T), T>>>(src, dst, buf0, buf2);
    k_bias<H, true><<<CDIV(N * H, T), T>>>(buf2, b_enc2, buf1);

    // ---- global mean pool + latent projection
    k_pool_init<<<CDIV(G * H, T), T>>>();
    k_pool_acc<<<CDIV(N * H, T), T>>>(batch, buf1);
    k_pool_cnt<<<CDIV(N, T), T>>>(batch);
    k_z<<<1, G * L>>>(W_proj, b_proj, out_z);

    // ---- decoder broadcast: d = relu(z[batch] @ W_dec_proj + b)
    k_dec_bcast<<<CDIV(N * H, T), T>>>(batch, W_dproj, b_dproj, buf1);

    // ---- dec0: matmul 64->64, aggregate, bias+relu
    k_matmul<H, H, false, false><<<CDIV(N, 256 / H), 256>>>(buf1, W_dec0, nullptr, buf0);
    k_selfinit<H><<<CDIV(N * H / 4, T), T>>>(buf0, buf2);
    k_scatter<H><<<CDIV(E * (H / 4), T), T>>>(src, dst, buf0, buf2);
    k_bias<H, true><<<CDIV(N * H, T), T>>>(buf2, b_dec0, buf1);

    // ---- dec1: matmul 64->32, aggregate (C=32) into d_out, add bias (no relu)
    k_matmul<H, IN, false, false><<<CDIV(N, 256 / IN), 256>>>(buf1, W_dec1, nullptr, buf0);
    k_selfinit<IN><<<CDIV(N * IN / 4, T), T>>>(buf0, out_recon);
    k_scatter<IN><<<CDIV(E * (IN / 4), T), T>>>(src, dst, buf0, out_recon);
    k_bias<IN, false><<<CDIV(N * IN, T), T>>>(out_recon, b_dec1, out_recon);
}

// round 2
// speedup vs baseline: 2.5422x; 2.5422x over previous
#include <cuda_runtime.h>

// Problem constants (fixed by the reference)
constexpr int N  = 100000;
constexpr int E  = 1600000;
constexpr int IN = 32;
constexpr int H  = 64;
constexpr int L  = 16;
constexpr int G  = 64;

constexpr int SCAN_CHUNK = 512;
constexpr int NB_SCAN = (N + SCAN_CHUNK - 1) / SCAN_CHUNK;  // 196

#define CDIV(a, b) (((a) + (b) - 1) / (b))

// ---------------- device scratch (no allocations allowed) ----------------
__device__ float g_buf0[N * H];
__device__ float g_buf1[N * H];
__device__ float g_dinv[N];
__device__ int   g_deg[N];        // degree histogram (no self loop)
__device__ int   g_rowptr[N + 1];
__device__ int   g_cursor[N];
__device__ int   g_srcs[E];       // src ids sorted by dst
__device__ int   g_bsum[256];
__device__ float g_pool[G * H];
__device__ float g_cnt[G];
__device__ float g_z[G * L];

// ---------------- degree histogram + dinv ----------------
__global__ void k_hist(const int* __restrict__ dst) {
    int e = blockIdx.x * blockDim.x + threadIdx.x;
    if (e < E) atomicAdd(&g_deg[dst[e]], 1);
}

__global__ void k_dinv() {
    int i = blockIdx.x * blockDim.x + threadIdx.x;
    if (i < N) g_dinv[i] = rsqrtf((float)g_deg[i] + 1.0f);
}

// ---------------- exclusive scan of g_deg -> g_rowptr ----------------
__global__ void k_scan1() {
    __shared__ int s[SCAN_CHUNK];
    int t = threadIdx.x;
    int i = blockIdx.x * SCAN_CHUNK + t;
    int v = (i < N) ? g_deg[i] : 0;
    s[t] = v;
    __syncthreads();
#pragma unroll
    for (int off = 1; off < SCAN_CHUNK; off <<= 1) {
        int x = (t >= off) ? s[t - off] : 0;
        __syncthreads();
        s[t] += x;
        __syncthreads();
    }
    if (i < N) g_rowptr[i] = s[t] - v;  // exclusive within chunk
    if (t == SCAN_CHUNK - 1) g_bsum[blockIdx.x] = s[t];
}

__global__ void k_scan2() {
    __shared__ int s[256];
    int t = threadIdx.x;
    int v = (t < NB_SCAN) ? g_bsum[t] : 0;
    s[t] = v;
    __syncthreads();
#pragma unroll
    for (int off = 1; off < 256; off <<= 1) {
        int x = (t >= off) ? s[t - off] : 0;
        __syncthreads();
        s[t] += x;
        __syncthreads();
    }
    if (t < NB_SCAN) g_bsum[t] = s[t] - v;  // exclusive block offsets
}

__global__ void k_scan3() {
    int i = blockIdx.x * blockDim.x + threadIdx.x;
    if (i < N) {
        int r = g_rowptr[i] + g_bsum[i / SCAN_CHUNK];
        g_rowptr[i] = r;
        g_cursor[i] = r;
    }
    if (i == 0) g_rowptr[N] = E;
}

__global__ void k_fill(const int* __restrict__ src, const int* __restrict__ dst) {
    int e = blockIdx.x * blockDim.x + threadIdx.x;
    if (e >= E) return;
    int pos = atomicAdd(&g_cursor[dst[e]], 1);
    g_srcs[pos] = src[e];
}

// ---------------- prescale: Y = X * dinv[row]  (C=32) ----------------
__global__ void k_prescale32(const float* __restrict__ X, float* __restrict__ Y) {
    int idx = blockIdx.x * blockDim.x + threadIdx.x;  // N*8
    if (idx >= N * 8) return;
    int i = idx >> 3;
    float d = g_dinv[i];
    float4 v = ((const float4*)X)[idx];
    float4 o = {v.x * d, v.y * d, v.z * d, v.w * d};
    ((float4*)Y)[idx] = o;
}

// ---------------- CSR gather:  Y[i] = dinv[i]*(sum_src X[src] + X[i]) ----------------
template <int C, bool BIAS, bool RELU>
__global__ void k_gather(const float* __restrict__ X, const float* __restrict__ bias,
                         float* __restrict__ Y) {
    constexpr int Q = C / 4;                 // threads per node
    constexpr int NPB = 256 / Q;             // nodes per block
    int t = threadIdx.x;
    int node = blockIdx.x * NPB + t / Q;
    int q = t % Q;
    if (node >= N) return;
    int beg = g_rowptr[node];
    int end = g_rowptr[node + 1];
    const float4* Xv = (const float4*)X;
    float4 acc = Xv[(size_t)node * Q + q];   // self term (X already dinv-scaled)
#pragma unroll 4
    for (int j = beg; j < end; j++) {
        int s = g_srcs[j];
        float4 v = Xv[(size_t)s * Q + q];
        acc.x += v.x; acc.y += v.y; acc.z += v.z; acc.w += v.w;
    }
    float d = g_dinv[node];
    acc.x *= d; acc.y *= d; acc.z *= d; acc.w *= d;
    if (BIAS) {
        float4 bv = ((const float4*)bias)[q];
        acc.x += bv.x; acc.y += bv.y; acc.z += bv.z; acc.w += bv.w;
    }
    if (RELU) {
        acc.x = fmaxf(acc.x, 0.f); acc.y = fmaxf(acc.y, 0.f);
        acc.z = fmaxf(acc.z, 0.f); acc.w = fmaxf(acc.w, 0.f);
    }
    ((float4*)Y)[(size_t)node * Q + q] = acc;
}

// ---------------- dense per-node matmul, 8-or-4 outputs per thread ----------------
// SCALE: multiply result by dinv[row] (produces X' for the gather)
template <int CIN, int COUT, bool SCALE, bool BIAS, bool RELU>
__global__ void k_mm(const float* __restrict__ X, const float* __restrict__ W,
                     const float* __restrict__ bias, float* __restrict__ Y) {
    constexpr int ROWS = 32;
    constexpr int TPR = 8;            // threads per row
    constexpr int CPT = COUT / TPR;   // cols per thread (8 for 64, 4 for 32)
    __shared__ float sW[CIN * COUT];
    __shared__ float sX[ROWS * CIN];
    int t = threadIdx.x;
    for (int i = t; i < CIN * COUT / 4; i += 256)
        ((float4*)sW)[i] = ((const float4*)W)[i];
    int row0 = blockIdx.x * ROWS;
    for (int i = t; i < ROWS * (CIN / 4); i += 256) {
        int r = row0 + i / (CIN / 4);
        ((float4*)sX)[i] = (r < N) ? ((const float4*)X)[(size_t)r * (CIN / 4) + i % (CIN / 4)]
                                   : make_float4(0.f, 0.f, 0.f, 0.f);
    }
    __syncthreads();
    int r = t / TPR;
    int c0 = (t % TPR) * CPT;
    int row = row0 + r;
    if (row >= N) return;
    float acc[CPT];
#pragma unroll
    for (int i = 0; i < CPT; i++) acc[i] = BIAS ? bias[c0 + i] : 0.f;
#pragma unroll
    for (int k = 0; k < CIN; k++) {
        float xv = sX[r * CIN + k];
#pragma unroll
        for (int i = 0; i < CPT; i++)
            acc[i] = fmaf(xv, sW[k * COUT + c0 + i], acc[i]);
    }
    float s = SCALE ? g_dinv[row] : 1.f;
#pragma unroll
    for (int v = 0; v < CPT / 4; v++) {
        float4 o;
        o.x = acc[v * 4 + 0] * s; o.y = acc[v * 4 + 1] * s;
        o.z = acc[v * 4 + 2] * s; o.w = acc[v * 4 + 3] * s;
        if (RELU) {
            o.x = fmaxf(o.x, 0.f); o.y = fmaxf(o.y, 0.f);
            o.z = fmaxf(o.z, 0.f); o.w = fmaxf(o.w, 0.f);
        }
        ((float4*)(Y + (size_t)row * COUT + c0))[v] = o;
    }
}

// ---------------- global mean pool (sorted batch, run-length accumulate) ----------------
__global__ void k_pool_acc(const int* __restrict__ batch, const float* __restrict__ Hf) {
    // block covers 128 nodes x 64 cols; thread: col c, rows stride 4
    int t = threadIdx.x;
    int c = t % 64;
    int base = blockIdx.x * 128;
    float acc = 0.f;
    int cur = -1;
    for (int j = t / 64; j < 128; j += 4) {
        int i = base + j;
        if (i >= N) break;
        int g = batch[i];
        if (g != cur) {
            if (cur >= 0) atomicAdd(&g_pool[cur * 64 + c], acc);
            cur = g; acc = 0.f;
        }
        acc += Hf[(size_t)i * 64 + c];
    }
    if (cur >= 0) atomicAdd(&g_pool[cur * 64 + c], acc);
}

__global__ void k_pool_cnt(const int* __restrict__ batch) {
    __shared__ int h[G];
    int t = threadIdx.x;
    if (t < G) h[t] = 0;
    __syncthreads();
    int i = blockIdx.x * blockDim.x + t;
    if (i < N) atomicAdd(&h[batch[i]], 1);
    __syncthreads();
    if (t < G && h[t] > 0) atomicAdd(&g_cnt[t], (float)h[t]);
}

// ---------------- latent projection: z = mean @ W_proj + b ----------------
__global__ void k_z(const float* __restrict__ Wp, const float* __restrict__ bp,
                    float* __restrict__ out_z) {
    int t = threadIdx.x;  // 1024 = G*L
    int g = t / L, l = t % L;
    float inv = 1.0f / fmaxf(g_cnt[g], 1.0f);
    float acc = bp[l];
#pragma unroll
    for (int c = 0; c < H; c++) acc = fmaf(g_pool[g * H + c] * inv, Wp[c * L + l], acc);
    g_z[t] = acc;
    out_z[t] = acc;
}

// ---------------- decoder broadcast: d = relu(z[batch] @ W_dec_proj + b) ----------------
__global__ void k_dec_bcast(const int* __restrict__ batch, const float* __restrict__ W,
                            const float* __restrict__ b, float* __restrict__ Y) {
    int idx = blockIdx.x * blockDim.x + threadIdx.x;
    if (idx >= N * H) return;
    int i = idx / H, c = idx % H;
    int gid = batch[i];
    float acc = b[c];
#pragma unroll
    for (int l = 0; l < L; l++) acc = fmaf(g_z[gid * L + l], W[l * H + c], acc);
    Y[idx] = fmaxf(acc, 0.0f);
}

// ---------------- launcher ----------------
extern "C" void kernel_launch(void* const* d_in, const int* in_sizes, int n_in,
                              void* d_out, int out_size) {
    const float* x       = (const float*)d_in[0];
    const int*   ei      = (const int*)d_in[1];
    const int*   src     = ei;
    const int*   dst     = ei + E;
    const int*   batch   = (const int*)d_in[2];
    const float* W_enc0  = (const float*)d_in[3];
    const float* b_enc0  = (const float*)d_in[4];
    const float* W_enc1  = (const float*)d_in[5];
    const float* b_enc1  = (const float*)d_in[6];
    const float* W_enc2  = (const float*)d_in[7];
    const float* b_enc2  = (const float*)d_in[8];
    const float* W_proj  = (const float*)d_in[9];
    const float* b_proj  = (const float*)d_in[10];
    const float* W_dproj = (const float*)d_in[11];
    const float* b_dproj = (const float*)d_in[12];
    const float* W_dec0  = (const float*)d_in[13];
    const float* b_dec0  = (const float*)d_in[14];
    const float* W_dec1  = (const float*)d_in[15];
    const float* b_dec1  = (const float*)d_in[16];

    float* out_recon = (float*)d_out;           // [N, IN]
    float* out_z     = (float*)d_out + N * IN;  // [G, L]

    float* buf0;  cudaGetSymbolAddress((void**)&buf0, g_buf0);
    float* buf1;  cudaGetSymbolAddress((void**)&buf1, g_buf1);
    int*   degp;  cudaGetSymbolAddress((void**)&degp, g_deg);
    float* poolp; cudaGetSymbolAddress((void**)&poolp, g_pool);
    float* cntp;  cudaGetSymbolAddress((void**)&cntp, g_cnt);

    const int T = 256;

    // ---- CSR build + dinv (amortized across all 5 aggregations)
    cudaMemsetAsync(degp, 0, N * sizeof(int));
    k_hist<<<CDIV(E, T), T>>>(dst);
    k_dinv<<<CDIV(N, T), T>>>();
    k_scan1<<<NB_SCAN, SCAN_CHUNK>>>();
    k_scan2<<<1, 256>>>();
    k_scan3<<<CDIV(N, T), T>>>();
    k_fill<<<CDIV(E, T), T>>>(src, dst);

    // ---- enc0: aggregate x at C=32, then 32->64 matmul + bias + relu
    k_prescale32<<<CDIV(N * 8, T), T>>>(x, buf0);
    k_gather<IN, false, false><<<CDIV(N, 32), 256>>>(buf0, nullptr, buf1);
    k_mm<IN, H, false, true, true><<<CDIV(N, 32), 256>>>(buf1, W_enc0, b_enc0, buf0);

    // ---- enc1: (dinv * XW), gather + bias + relu
    k_mm<H, H, true, false, false><<<CDIV(N, 32), 256>>>(buf0, W_enc1, nullptr, buf1);
    k_gather<H, true, true><<<CDIV(N, 16), 256>>>(buf1, b_enc1, buf0);

    // ---- enc2
    k_mm<H, H, true, false, false><<<CDIV(N, 32), 256>>>(buf0, W_enc2, nullptr, buf1);
    k_gather<H, true, true><<<CDIV(N, 16), 256>>>(buf1, b_enc2, buf0);

    // ---- global mean pool + latent projection
    cudaMemsetAsync(poolp, 0, G * H * sizeof(float));
    cudaMemsetAsync(cntp, 0, G * sizeof(float));
    k_pool_acc<<<CDIV(N, 128), 256>>>(batch, buf0);
    k_pool_cnt<<<CDIV(N, T), T>>>(batch);
    k_z<<<1, G * L>>>(W_proj, b_proj, out_z);

    // ---- decoder broadcast
    k_dec_bcast<<<CDIV(N * H, T), T>>>(batch, W_dproj, b_dproj, buf0);

    // ---- dec0
    k_mm<H, H, true, false, false><<<CDIV(N, 32), 256>>>(buf0, W_dec0, nullptr, buf1);
    k_gather<H, true, true><<<CDIV(N, 16), 256>>>(buf1, b_dec0, buf0);

    // ---- dec1: 64->32 matmul (dinv-scaled), gather at C=32 straight into d_out
    k_mm<H, IN, true, false, false><<<CDIV(N, 32), 256>>>(buf0, W_dec1, nullptr, buf1);
    k_gather<IN, true, false><<<CDIV(N, 32), 256>>>(buf1, b_dec1, out_recon);
}

// round 3
// speedup vs baseline: 4.5355x; 1.7841x over previous
#include <cuda_runtime.h>

// Problem constants (fixed by the reference)
constexpr int N  = 100000;
constexpr int E  = 1600000;
constexpr int IN = 32;
constexpr int H  = 64;
constexpr int L  = 16;
constexpr int G  = 64;

constexpr int SCAN_CHUNK = 512;
constexpr int NB_SCAN = (N + SCAN_CHUNK - 1) / SCAN_CHUNK;  // 196

#define CDIV(a, b) (((a) + (b) - 1) / (b))

// ---------------- device scratch (no allocations allowed) ----------------
__device__ float g_buf0[N * H];
__device__ float g_buf1[N * H];
__device__ float g_dinv[N];
__device__ int   g_deg[N];
__device__ int   g_rowptr[N + 1];
__device__ int   g_cursor[N];
__device__ int   g_srcs[E];
__device__ int   g_bsum[256];
__device__ float g_pool[G * H];
__device__ float g_cnt[G];
__device__ float g_z[G * L];

// ---------------- degree histogram ----------------
__global__ void k_hist(const int* __restrict__ dst) {
    int e = blockIdx.x * blockDim.x + threadIdx.x;
    if (e < E) atomicAdd(&g_deg[dst[e]], 1);
}

// ---------------- scan (also computes dinv from deg) ----------------
__global__ void k_scan1() {
    __shared__ int s[SCAN_CHUNK];
    int t = threadIdx.x;
    int i = blockIdx.x * SCAN_CHUNK + t;
    int v = (i < N) ? g_deg[i] : 0;
    if (i < N) g_dinv[i] = rsqrtf((float)v + 1.0f);
    s[t] = v;
    __syncthreads();
#pragma unroll
    for (int off = 1; off < SCAN_CHUNK; off <<= 1) {
        int x = (t >= off) ? s[t - off] : 0;
        __syncthreads();
        s[t] += x;
        __syncthreads();
    }
    if (i < N) g_rowptr[i] = s[t] - v;
    if (t == SCAN_CHUNK - 1) g_bsum[blockIdx.x] = s[t];
}

__global__ void k_scan2() {
    __shared__ int s[256];
    int t = threadIdx.x;
    int v = (t < NB_SCAN) ? g_bsum[t] : 0;
    s[t] = v;
    __syncthreads();
#pragma unroll
    for (int off = 1; off < 256; off <<= 1) {
        int x = (t >= off) ? s[t - off] : 0;
        __syncthreads();
        s[t] += x;
        __syncthreads();
    }
    if (t < NB_SCAN) g_bsum[t] = s[t] - v;
}

__global__ void k_scan3() {
    int i = blockIdx.x * blockDim.x + threadIdx.x;
    if (i < N) {
        int r = g_rowptr[i] + g_bsum[i / SCAN_CHUNK];
        g_rowptr[i] = r;
        g_cursor[i] = r;
    }
    if (i == 0) g_rowptr[N] = E;
}

__global__ void k_fill(const int* __restrict__ src, const int* __restrict__ dst) {
    int e = blockIdx.x * blockDim.x + threadIdx.x;
    if (e >= E) return;
    int pos = atomicAdd(&g_cursor[dst[e]], 1);
    g_srcs[pos] = src[e];
}

// ---------------- prescale: Y = X * dinv[row]  (C=32) ----------------
__global__ void k_prescale32(const float* __restrict__ X, float* __restrict__ Y) {
    int idx = blockIdx.x * blockDim.x + threadIdx.x;
    if (idx >= N * 8) return;
    int i = idx >> 3;
    float d = g_dinv[i];
    float4 v = ((const float4*)X)[idx];
    float4 o = {v.x * d, v.y * d, v.z * d, v.w * d};
    ((float4*)Y)[idx] = o;
}

// ---------------- CSR gather:  Y[i] = dinv[i]*(sum_src X[src] + X[i]) ----------------
template <int C, bool BIAS, bool RELU>
__global__ void k_gather(const float* __restrict__ X, const float* __restrict__ bias,
                         float* __restrict__ Y) {
    constexpr int Q = C / 4;
    constexpr int NPB = 256 / Q;
    int t = threadIdx.x;
    int node = blockIdx.x * NPB + t / Q;
    int q = t % Q;
    if (node >= N) return;
    int beg = g_rowptr[node];
    int end = g_rowptr[node + 1];
    const float4* Xv = (const float4*)X;
    float4 acc = Xv[(size_t)node * Q + q];
#pragma unroll 4
    for (int j = beg; j < end; j++) {
        int s = g_srcs[j];
        float4 v = Xv[(size_t)s * Q + q];
        acc.x += v.x; acc.y += v.y; acc.z += v.z; acc.w += v.w;
    }
    float d = g_dinv[node];
    acc.x *= d; acc.y *= d; acc.z *= d; acc.w *= d;
    if (BIAS) {
        float4 bv = ((const float4*)bias)[q];
        acc.x += bv.x; acc.y += bv.y; acc.z += bv.z; acc.w += bv.w;
    }
    if (RELU) {
        acc.x = fmaxf(acc.x, 0.f); acc.y = fmaxf(acc.y, 0.f);
        acc.z = fmaxf(acc.z, 0.f); acc.w = fmaxf(acc.w, 0.f);
    }
    ((float4*)Y)[(size_t)node * Q + q] = acc;
}

// ---------------- register-tiled per-node matmul ----------------
// Block: 256 threads, 256 rows. Thread computes 8 rows x CPT_C cols.
// Thread grid: 8 col-groups x 32 row-groups. ~1 B of LDS per FMA -> FMA-bound.
template <int CIN, int COUT, bool SCALE, bool BIAS, bool RELU>
__global__ void __launch_bounds__(256, 2)
k_mm(const float* __restrict__ X, const float* __restrict__ W,
     const float* __restrict__ bias, float* __restrict__ Y) {
    constexpr int ROWS = 256;
    constexpr int CPT_C = COUT / 8;     // 8 for COUT=64, 4 for COUT=32
    constexpr int XPITCH = CIN + 1;     // +1 pad: row-groups hit distinct banks
    extern __shared__ float smem[];
    float* sX = smem;                    // ROWS * XPITCH
    float* sW = smem + ROWS * XPITCH;    // CIN * COUT

    int t = threadIdx.x;
    int row0 = blockIdx.x * ROWS;

    // load W (float4, coalesced)
    for (int i = t; i < CIN * COUT / 4; i += 256)
        ((float4*)sW)[i] = ((const float4*)W)[i];
    // load X into padded smem (scalar, coalesced in k)
    for (int i = t; i < ROWS * CIN; i += 256) {
        int r = i / CIN, k = i % CIN;
        int row = row0 + r;
        sX[r * XPITCH + k] = (row < N) ? X[(size_t)row * CIN + k] : 0.0f;
    }
    __syncthreads();

    int tc = t % 8;            // col-group
    int tr = t / 8;            // row-group
    int c0 = tc * CPT_C;
    int r0 = tr * 8;

    float acc[8][CPT_C];
#pragma unroll
    for (int i = 0; i < 8; i++)
#pragma unroll
        for (int j = 0; j < CPT_C; j++) acc[i][j] = 0.0f;

#pragma unroll 8
    for (int k = 0; k < CIN; k++) {
        float a[8];
#pragma unroll
        for (int i = 0; i < 8; i++) a[i] = sX[(r0 + i) * XPITCH + k];
        float b[CPT_C];
#pragma unroll
        for (int v = 0; v < CPT_C / 4; v++)
            *(float4*)(b + v * 4) = *(const float4*)(sW + k * COUT + c0 + v * 4);
#pragma unroll
        for (int i = 0; i < 8; i++)
#pragma unroll
            for (int j = 0; j < CPT_C; j++)
                acc[i][j] = fmaf(a[i], b[j], acc[i][j]);
    }

    float bv[CPT_C];
    if (BIAS) {
#pragma unroll
        for (int v = 0; v < CPT_C / 4; v++)
            *(float4*)(bv + v * 4) = *(const float4*)(bias + c0 + v * 4);
    }
#pragma unroll
    for (int i = 0; i < 8; i++) {
        int row = row0 + r0 + i;
        if (row >= N) continue;
        float s = SCALE ? g_dinv[row] : 1.0f;
#pragma unroll
        for (int v = 0; v < CPT_C / 4; v++) {
            float4 o;
            o.x = acc[i][v * 4 + 0] * s;
            o.y = acc[i][v * 4 + 1] * s;
            o.z = acc[i][v * 4 + 2] * s;
            o.w = acc[i][v * 4 + 3] * s;
            if (BIAS) { o.x += bv[v*4+0]; o.y += bv[v*4+1]; o.z += bv[v*4+2]; o.w += bv[v*4+3]; }
            if (RELU) {
                o.x = fmaxf(o.x, 0.f); o.y = fmaxf(o.y, 0.f);
                o.z = fmaxf(o.z, 0.f); o.w = fmaxf(o.w, 0.f);
            }
            *(float4*)(Y + (size_t)row * COUT + c0 + v * 4) = o;
        }
    }
}

// ---------------- global mean pool (sorted batch, run-length) + counts ----------------
__global__ void k_pool_acc(const int* __restrict__ batch, const float* __restrict__ Hf) {
    int t = threadIdx.x;
    int c = t % 64;
    int base = blockIdx.x * 128;
    float acc = 0.f;
    float cntacc = 0.f;
    int cur = -1;
    for (int j = t / 64; j < 128; j += 4) {
        int i = base + j;
        if (i >= N) break;
        int g = batch[i];
        if (g != cur) {
            if (cur >= 0) {
                atomicAdd(&g_pool[cur * 64 + c], acc);
                if (c == 0) atomicAdd(&g_cnt[cur], cntacc);
            }
            cur = g; acc = 0.f; cntacc = 0.f;
        }
        acc += Hf[(size_t)i * 64 + c];
        cntacc += 1.f;
    }
    if (cur >= 0) {
        atomicAdd(&g_pool[cur * 64 + c], acc);
        if (c == 0) atomicAdd(&g_cnt[cur], cntacc);
    }
}

// ---------------- latent projection: z = mean @ W_proj + b ----------------
__global__ void k_z(const float* __restrict__ Wp, const float* __restrict__ bp,
                    float* __restrict__ out_z) {
    int t = threadIdx.x;  // 1024 = G*L
    int g = t / L, l = t % L;
    float inv = 1.0f / fmaxf(g_cnt[g], 1.0f);
    float acc = bp[l];
#pragma unroll
    for (int c = 0; c < H; c++) acc = fmaf(g_pool[g * H + c] * inv, Wp[c * L + l], acc);
    g_z[t] = acc;
    out_z[t] = acc;
}

// ---------------- decoder broadcast: d = relu(z[batch] @ W_dec_proj + b), x4 ----------------
__global__ void k_dec_bcast(const int* __restrict__ batch, const float* __restrict__ W,
                            const float* __restrict__ b, float* __restrict__ Y) {
    int idx = blockIdx.x * blockDim.x + threadIdx.x;  // N * 16
    if (idx >= N * 16) return;
    int i = idx >> 4, v = idx & 15;
    int gid = batch[i];
    float4 acc = ((const float4*)b)[v];
#pragma unroll
    for (int l = 0; l < L; l++) {
        float zl = g_z[gid * L + l];
        float4 w = ((const float4*)W)[l * 16 + v];
        acc.x = fmaf(zl, w.x, acc.x); acc.y = fmaf(zl, w.y, acc.y);
        acc.z = fmaf(zl, w.z, acc.z); acc.w = fmaf(zl, w.w, acc.w);
    }
    acc.x = fmaxf(acc.x, 0.f); acc.y = fmaxf(acc.y, 0.f);
    acc.z = fmaxf(acc.z, 0.f); acc.w = fmaxf(acc.w, 0.f);
    ((float4*)Y)[idx] = acc;
}

// ---------------- launcher ----------------
extern "C" void kernel_launch(void* const* d_in, const int* in_sizes, int n_in,
                              void* d_out, int out_size) {
    const float* x       = (const float*)d_in[0];
    const int*   ei      = (const int*)d_in[1];
    const int*   src     = ei;
    const int*   dst     = ei + E;
    const int*   batch   = (const int*)d_in[2];
    const float* W_enc0  = (const float*)d_in[3];
    const float* b_enc0  = (const float*)d_in[4];
    const float* W_enc1  = (const float*)d_in[5];
    const float* b_enc1  = (const float*)d_in[6];
    const float* W_enc2  = (const float*)d_in[7];
    const float* b_enc2  = (const float*)d_in[8];
    const float* W_proj  = (const float*)d_in[9];
    const float* b_proj  = (const float*)d_in[10];
    const float* W_dproj = (const float*)d_in[11];
    const float* b_dproj = (const float*)d_in[12];
    const float* W_dec0  = (const float*)d_in[13];
    const float* b_dec0  = (const float*)d_in[14];
    const float* W_dec1  = (const float*)d_in[15];
    const float* b_dec1  = (const float*)d_in[16];

    float* out_recon = (float*)d_out;           // [N, IN]
    float* out_z     = (float*)d_out + N * IN;  // [G, L]

    float* buf0;  cudaGetSymbolAddress((void**)&buf0, g_buf0);
    float* buf1;  cudaGetSymbolAddress((void**)&buf1, g_buf1);
    int*   degp;  cudaGetSymbolAddress((void**)&degp, g_deg);
    float* poolp; cudaGetSymbolAddress((void**)&poolp, g_pool);
    float* cntp;  cudaGetSymbolAddress((void**)&cntp, g_cnt);

    const int T = 256;

    // dynamic smem sizes for the register-tiled GEMMs
    constexpr int SM_64_64 = (256 * 65 + 64 * 64) * 4;   // 82.9 KB
    constexpr int SM_32_64 = (256 * 33 + 32 * 64) * 4;   // 41.8 KB
    constexpr int SM_64_32 = (256 * 65 + 64 * 32) * 4;   // 74.8 KB
    static bool attr_done = false;
    if (!attr_done) {
        cudaFuncSetAttribute((const void*)k_mm<IN, H, false, true, true>,
                             cudaFuncAttributeMaxDynamicSharedMemorySize, SM_32_64);
        cudaFuncSetAttribute((const void*)k_mm<H, H, true, false, false>,
                             cudaFuncAttributeMaxDynamicSharedMemorySize, SM_64_64);
        cudaFuncSetAttribute((const void*)k_mm<H, IN, true, false, false>,
                             cudaFuncAttributeMaxDynamicSharedMemorySize, SM_64_32);
        attr_done = true;
    }

    // ---- CSR build + dinv
    cudaMemsetAsync(degp, 0, N * sizeof(int));
    k_hist<<<CDIV(E, T), T>>>(dst);
    k_scan1<<<NB_SCAN, SCAN_CHUNK>>>();
    k_scan2<<<1, 256>>>();
    k_scan3<<<CDIV(N, T), T>>>();
    k_fill<<<CDIV(E, T), T>>>(src, dst);

    const int MMB = CDIV(N, 256);

    // ---- enc0: aggregate x at C=32, then 32->64 matmul (+bias+relu)
    k_prescale32<<<CDIV(N * 8, T), T>>>(x, buf0);
    k_gather<IN, false, false><<<CDIV(N, 32), 256>>>(buf0, nullptr, buf1);
    k_mm<IN, H, false, true, true><<<MMB, 256, SM_32_64>>>(buf1, W_enc0, b_enc0, buf0);

    // ---- enc1
    k_mm<H, H, true, false, false><<<MMB, 256, SM_64_64>>>(buf0, W_enc1, nullptr, buf1);
    k_gather<H, true, true><<<CDIV(N, 16), 256>>>(buf1, b_enc1, buf0);

    // ---- enc2
    k_mm<H, H, true, false, false><<<MMB, 256, SM_64_64>>>(buf0, W_enc2, nullptr, buf1);
    k_gather<H, true, true><<<CDIV(N, 16), 256>>>(buf1, b_enc2, buf0);

    // ---- global mean pool + latent projection
    cudaMemsetAsync(poolp, 0, G * H * sizeof(float));
    cudaMemsetAsync(cntp, 0, G * sizeof(float));
    k_pool_acc<<<CDIV(N, 128), 256>>>(batch, buf0);
    k_z<<<1, G * L>>>(W_proj, b_proj, out_z);

    // ---- decoder broadcast
    k_dec_bcast<<<CDIV(N * 16, T), T>>>(batch, W_dproj, b_dproj, buf0);

    // ---- dec0
    k_mm<H, H, true, false, false><<<MMB, 256, SM_64_64>>>(buf0, W_dec0, nullptr, buf1);
    k_gather<H, true, true><<<CDIV(N, 16), 256>>>(buf1, b_dec0, buf0);

    // ---- dec1: 64->32 matmul (dinv-scaled), gather at C=32 into d_out
    k_mm<H, IN, true, false, false><<<MMB, 256, SM_64_32>>>(buf0, W_dec1, nullptr, buf1);
    k_gather<IN, true, false><<<CDIV(N, 32), 256>>>(buf1, b_dec1, out_recon);
}